// round 1
// baseline (speedup 1.0000x reference)
#include <cuda_runtime.h>
#include <math.h>

#define FDIM 128
#define GMAX 50000
#define CAP  192
#define OVF_MAX 4096

// ---------------- device scratch (no allocations allowed) ----------------
__device__ int g_cnt[GMAX];             // per-segment node count
__device__ int g_perm[(size_t)GMAX * CAP]; // bucketed node indices (38.4 MB)
__device__ int g_ovf[OVF_MAX];          // overflow node list (should stay empty)
__device__ int g_novf;                  // overflow count
__device__ int g_is64;                  // 1 if seg_ids are int64, 0 if int32

// ---------------- kernel 1: init counters + dtype sniff ----------------
__global__ void init_kernel(const unsigned int* __restrict__ seg_words, int G) {
    int i = blockIdx.x * blockDim.x + threadIdx.x;
    if (i < G) g_cnt[i] = 0;
    if (blockIdx.x == 0 && threadIdx.x == 0) {
        g_novf = 0;
        // If seg_ids are int64 (values in [0,50000)), every odd 32-bit word of
        // the first 64 elements is the zero high-half. If int32, those words
        // are independent segment ids; all-64-zero has prob (1/50000)^64 ~ 0.
        unsigned int acc = 0;
        #pragma unroll
        for (int k = 0; k < 64; k++) acc |= seg_words[2 * k + 1];
        g_is64 = (acc == 0u) ? 1 : 0;
    }
}

// ---------------- kernel 2: scatter nodes into per-segment buckets ----------------
__global__ void scatter_kernel(const void* __restrict__ seg, int N) {
    int i = blockIdx.x * blockDim.x + threadIdx.x;
    if (i >= N) return;
    int s;
    if (g_is64) s = (int)((const long long*)seg)[i];
    else        s = ((const int*)seg)[i];
    int slot = atomicAdd(&g_cnt[s], 1);
    if (slot < CAP) {
        g_perm[(size_t)s * CAP + slot] = i;
    } else {
        int o = atomicAdd(&g_novf, 1);
        if (o < OVF_MAX) g_ovf[o] = i;
    }
}

// ---------------- kernel 3: fused gather-pool + MLP ----------------
// One warp per segment. Lane l owns features [4l, 4l+4).
__global__ void __launch_bounds__(256) pool_mlp_kernel(
    const float* __restrict__ h,
    const void*  __restrict__ seg,
    const float* __restrict__ W1,   // [128,128] row-major: W1[k][j]
    const float* __restrict__ b1,   // [128]
    const float* __restrict__ W2,   // [128]
    const float* __restrict__ b2,   // [1]
    float* __restrict__ y, int G)
{
    __shared__ float sp[8][FDIM];   // pooled row per warp
    const int warp = threadIdx.x >> 5;
    const int lane = threadIdx.x & 31;
    const int g = blockIdx.x * 8 + warp;
    if (g >= G) return;             // uniform per warp

    const int n = min(g_cnt[g], CAP);
    const int* pm = &g_perm[(size_t)g * CAP];

    float4 a0 = make_float4(0.f, 0.f, 0.f, 0.f);
    float4 a1 = a0, a2 = a0, a3 = a0;

    int i = 0;
    for (; i + 4 <= n; i += 4) {
        int n0 = __ldg(pm + i + 0);
        int n1 = __ldg(pm + i + 1);
        int n2 = __ldg(pm + i + 2);
        int n3 = __ldg(pm + i + 3);
        float4 v0 = __ldcs((const float4*)(h + (size_t)n0 * FDIM) + lane);
        float4 v1 = __ldcs((const float4*)(h + (size_t)n1 * FDIM) + lane);
        float4 v2 = __ldcs((const float4*)(h + (size_t)n2 * FDIM) + lane);
        float4 v3 = __ldcs((const float4*)(h + (size_t)n3 * FDIM) + lane);
        a0.x += v0.x; a0.y += v0.y; a0.z += v0.z; a0.w += v0.w;
        a1.x += v1.x; a1.y += v1.y; a1.z += v1.z; a1.w += v1.w;
        a2.x += v2.x; a2.y += v2.y; a2.z += v2.z; a2.w += v2.w;
        a3.x += v3.x; a3.y += v3.y; a3.z += v3.z; a3.w += v3.w;
    }
    for (; i < n; i++) {
        int nd = __ldg(pm + i);
        float4 v = __ldcs((const float4*)(h + (size_t)nd * FDIM) + lane);
        a0.x += v.x; a0.y += v.y; a0.z += v.z; a0.w += v.w;
    }

    // Overflow nodes (near-impossible path, kept for correctness)
    int nov = g_novf;
    if (nov > 0) {
        nov = min(nov, OVF_MAX);
        int is64 = g_is64;
        for (int k = 0; k < nov; k++) {
            int nd = g_ovf[k];
            int s = is64 ? (int)((const long long*)seg)[nd]
                         : ((const int*)seg)[nd];
            if (s == g) {
                float4 v = __ldcs((const float4*)(h + (size_t)nd * FDIM) + lane);
                a0.x += v.x; a0.y += v.y; a0.z += v.z; a0.w += v.w;
            }
        }
    }

    float4 acc;
    acc.x = (a0.x + a1.x) + (a2.x + a3.x);
    acc.y = (a0.y + a1.y) + (a2.y + a3.y);
    acc.z = (a0.z + a1.z) + (a2.z + a3.z);
    acc.w = (a0.w + a1.w) + (a2.w + a3.w);

    // Stage pooled row into smem for broadcast in the GEMV
    ((float4*)sp[warp])[lane] = acc;
    __syncwarp();

    // hidden[4l..4l+3] = tanh(b1 + pooled @ W1)
    float4 bb = __ldg((const float4*)b1 + lane);
    float h0 = bb.x, h1 = bb.y, h2 = bb.z, h3 = bb.w;
    const float4* W1v = (const float4*)W1;   // row k, lane chunk: W1v[k*32 + lane]
    #pragma unroll 4
    for (int k = 0; k < FDIM; k++) {
        float pk = sp[warp][k];
        float4 w = __ldg(W1v + k * 32 + lane);
        h0 = fmaf(pk, w.x, h0);
        h1 = fmaf(pk, w.y, h1);
        h2 = fmaf(pk, w.z, h2);
        h3 = fmaf(pk, w.w, h3);
    }
    h0 = tanhf(h0); h1 = tanhf(h1); h2 = tanhf(h2); h3 = tanhf(h3);

    float4 w2 = __ldg((const float4*)W2 + lane);
    float part = h0 * w2.x + h1 * w2.y + h2 * w2.z + h3 * w2.w;
    #pragma unroll
    for (int off = 16; off; off >>= 1)
        part += __shfl_down_sync(0xffffffffu, part, off);
    if (lane == 0) y[g] = part + __ldg(b2);
}

// ---------------- launch ----------------
extern "C" void kernel_launch(void* const* d_in, const int* in_sizes, int n_in,
                              void* d_out, int out_size) {
    const float* h   = (const float*)d_in[0];
    const void*  seg = d_in[1];
    const int N = in_sizes[0] / FDIM;
    const int G = out_size;          // OUT = 1

    // Locate W1 by its unique size (num_graphs scalar may or may not be present)
    int iw = -1;
    for (int i = 2; i < n_in; i++) {
        if (in_sizes[i] == FDIM * FDIM) { iw = i; break; }
    }
    const float* W1 = (const float*)d_in[iw];
    const float* b1 = (const float*)d_in[iw + 1];
    const float* W2 = (const float*)d_in[iw + 2];
    const float* b2 = (const float*)d_in[iw + 3];
    float* y = (float*)d_out;

    init_kernel<<<(G + 1023) / 1024, 1024>>>((const unsigned int*)seg, G);
    scatter_kernel<<<(N + 255) / 256, 256>>>(seg, N);
    pool_mlp_kernel<<<(G + 7) / 8, 256>>>(h, seg, W1, b1, W2, b2, y, G);
}